// round 2
// baseline (speedup 1.0000x reference)
#include <cuda_runtime.h>
#include <math.h>

// ---------------------------------------------------------------------------
// Problem constants
// ---------------------------------------------------------------------------
#define T_STEPS 128
#define IN_D    512
#define H_D     512
#define B_D     256
#define TAG     64
#define LM_D    200
#define POS_D   6
#define CAP_D   3
#define HB      (H_D * B_D)          // 131072
#define GATE_M  (4 * H_D)            // 2048
#define TI_M    (3 * H_D)            // 1536
#define GB_M    (GATE_M + TI_M)      // 3584

// Output section offsets (floats) in d_out: lf, lc, y_fact, y_cond, Ts
#define SEC_Y   ((size_t)B_D * T_STEPS * TAG)       // 2,097,152
#define OFF_LF  ((size_t)0)
#define OFF_LC  (SEC_Y)
#define OFF_YF  (2 * SEC_Y)
#define OFF_YC  (3 * SEC_Y)
#define OFF_TS  (4 * SEC_Y)

// ---------------------------------------------------------------------------
// Scratch (device globals; no allocations allowed)
// ---------------------------------------------------------------------------
__device__ float g_x   [(size_t)T_STEPS * IN_D  * B_D];   //  67 MB
__device__ float g_ii  [(size_t)T_STEPS * GATE_M * B_D];  // 268 MB
__device__ float g_tadd[(size_t)T_STEPS * H_D  * B_D];    //  67 MB
__device__ float g_Ts  [(size_t)T_STEPS * H_D  * B_D];    //  67 MB
__device__ float g_gbuf[(size_t)GB_M * B_D];              // hi (2048 rows) + ti (1536 rows)
__device__ float g_c   [HB];
__device__ float g_h   [HB];
__device__ float g_opre[HB];

__device__ __forceinline__ float sigm(float x) { return 1.f / (1.f + expf(-x)); }

// ---------------------------------------------------------------------------
// Generic tiled SGEMM tile accumulator.
// C tile = A (MxK) @ B (KxN), A row-major (or transposed, AT=true: A is KxM).
// 256 threads/CTA. Thread (tx = tid%16, ty = tid/16) owns a TMxTN sub-tile.
// K is bound-checked (zero fill) so K need not be a multiple of BK.
// M tile and N tile are assumed fully in range (all our dims are multiples).
// ---------------------------------------------------------------------------
template <int BM, int BN, int BK, int TM, int TN, bool AT>
__device__ __forceinline__ void gemm_tile(const float* __restrict__ A,
                                          const float* __restrict__ B,
                                          int K, int lda, int ldb,
                                          int m0, int n0,
                                          float (&acc)[TM][TN], float* sm)
{
    static_assert((BM / TM) * (BN / TN) == 256, "256 threads required");
    float (*As)[BM] = (float (*)[BM])sm;
    float (*Bs)[BN] = (float (*)[BN])(sm + BK * BM);
    const int tid = threadIdx.x;
    const int tx  = tid % (BN / TN);
    const int ty  = tid / (BN / TN);
    constexpr int LA = (BM * BK) / 256;
    constexpr int LB = (BK * BN) / 256;

    for (int k0 = 0; k0 < K; k0 += BK) {
#pragma unroll
        for (int i = 0; i < LA; i++) {
            int li = tid + i * 256;
            if (AT) {
                int k = li / BM, m = li % BM;
                int kk = k0 + k;
                As[k][m] = (kk < K) ? A[(size_t)kk * lda + (m0 + m)] : 0.f;
            } else {
                int m = li / BK, k = li % BK;
                int kk = k0 + k;
                As[k][m] = (kk < K) ? A[(size_t)(m0 + m) * lda + kk] : 0.f;
            }
        }
#pragma unroll
        for (int i = 0; i < LB; i++) {
            int li = tid + i * 256;
            int k = li / BN, n = li % BN;
            int kk = k0 + k;
            Bs[k][n] = (kk < K) ? B[(size_t)kk * ldb + (n0 + n)] : 0.f;
        }
        __syncthreads();
#pragma unroll
        for (int k = 0; k < BK; k++) {
            float av[TM], bv[TN];
#pragma unroll
            for (int i = 0; i < TM; i++) av[i] = As[k][ty * TM + i];
#pragma unroll
            for (int j = 0; j < TN; j++) bv[j] = Bs[k][tx * TN + j];
#pragma unroll
            for (int i = 0; i < TM; i++)
#pragma unroll
                for (int j = 0; j < TN; j++) acc[i][j] += av[i] * bv[j];
        }
        __syncthreads();
    }
}

// ---------------------------------------------------------------------------
// Phase A kernels (parallel over t)
// ---------------------------------------------------------------------------

// x[t,i,b] = inputs + w_lmw^T@lm + w_posw^T@pos + w_capw^T@cap
__global__ void __launch_bounds__(256)
k_x(const float* __restrict__ inputs, const float* __restrict__ lms,
    const float* __restrict__ poses, const float* __restrict__ caps,
    const float* __restrict__ w_lmw, const float* __restrict__ w_posw,
    const float* __restrict__ w_capw)
{
    __shared__ float sm[16 * 128];
    int t = blockIdx.z, m0 = blockIdx.y * 64, n0 = blockIdx.x * 64;
    float acc[4][4] = {};
    gemm_tile<64,64,16,4,4,true>(w_lmw,  lms   + (size_t)t * LM_D  * B_D, LM_D,  IN_D, B_D, m0, n0, acc, sm);
    gemm_tile<64,64,16,4,4,true>(w_posw, poses + (size_t)t * POS_D * B_D, POS_D, IN_D, B_D, m0, n0, acc, sm);
    gemm_tile<64,64,16,4,4,true>(w_capw, caps  + (size_t)t * CAP_D * B_D, CAP_D, IN_D, B_D, m0, n0, acc, sm);
    int tx = threadIdx.x % 16, ty = threadIdx.x / 16;
    size_t base = (size_t)t * IN_D * B_D;
#pragma unroll
    for (int i = 0; i < 4; i++)
#pragma unroll
        for (int j = 0; j < 4; j++) {
            size_t idx = base + (size_t)(m0 + ty * 4 + i) * B_D + (n0 + tx * 4 + j);
            g_x[idx] = acc[i][j] + inputs[idx];
        }
}

// t_add[t,h,b] = w_lmt@lm + w_post@pos + w_capt@cap
__global__ void __launch_bounds__(256)
k_tadd(const float* __restrict__ lms, const float* __restrict__ poses,
       const float* __restrict__ caps, const float* __restrict__ w_lmt,
       const float* __restrict__ w_post, const float* __restrict__ w_capt)
{
    __shared__ float sm[16 * 128];
    int t = blockIdx.z, m0 = blockIdx.y * 64, n0 = blockIdx.x * 64;
    float acc[4][4] = {};
    gemm_tile<64,64,16,4,4,false>(w_lmt,  lms   + (size_t)t * LM_D  * B_D, LM_D,  LM_D,  B_D, m0, n0, acc, sm);
    gemm_tile<64,64,16,4,4,false>(w_post, poses + (size_t)t * POS_D * B_D, POS_D, POS_D, B_D, m0, n0, acc, sm);
    gemm_tile<64,64,16,4,4,false>(w_capt, caps  + (size_t)t * CAP_D * B_D, CAP_D, CAP_D, B_D, m0, n0, acc, sm);
    int tx = threadIdx.x % 16, ty = threadIdx.x / 16;
    size_t base = (size_t)t * H_D * B_D;
#pragma unroll
    for (int i = 0; i < 4; i++)
#pragma unroll
        for (int j = 0; j < 4; j++)
            g_tadd[base + (size_t)(m0 + ty * 4 + i) * B_D + (n0 + tx * 4 + j)] = acc[i][j];
}

// ii_all[t] = w_ii @ x[t]
__global__ void __launch_bounds__(256)
k_ii(const float* __restrict__ w_ii)
{
    __shared__ float sm[16 * 128];
    int t = blockIdx.z, m0 = blockIdx.y * 64, n0 = blockIdx.x * 64;
    float acc[4][4] = {};
    gemm_tile<64,64,16,4,4,false>(w_ii, g_x + (size_t)t * IN_D * B_D, IN_D, IN_D, B_D, m0, n0, acc, sm);
    int tx = threadIdx.x % 16, ty = threadIdx.x / 16;
    size_t base = (size_t)t * GATE_M * B_D;
#pragma unroll
    for (int i = 0; i < 4; i++)
#pragma unroll
        for (int j = 0; j < 4; j++)
            g_ii[base + (size_t)(m0 + ty * 4 + i) * B_D + (n0 + tx * 4 + j)] = acc[i][j];
}

// ---------------------------------------------------------------------------
// Recurrent step kernels
// ---------------------------------------------------------------------------

// gbuf[0:2048)   = w_hi @ h_prev
// gbuf[2048:3584) = w_ti @ T_prev
__global__ void __launch_bounds__(256)
k_hi_ti(const float* __restrict__ w_hi, const float* __restrict__ w_ti,
        const float* __restrict__ t0, int t)
{
    __shared__ float sm[16 * 128];
    int n0 = blockIdx.x * 64, m0 = blockIdx.y * 64;
    const float* Tprev = (t == 0) ? t0 : (g_Ts + (size_t)(t - 1) * HB);
    float acc[4][4] = {};
    if (m0 < GATE_M)
        gemm_tile<64,64,16,4,4,false>(w_hi, g_h,   H_D, H_D, B_D, m0,          n0, acc, sm);
    else
        gemm_tile<64,64,16,4,4,false>(w_ti, Tprev, H_D, H_D, B_D, m0 - GATE_M, n0, acc, sm);
    int tx = threadIdx.x % 16, ty = threadIdx.x / 16;
#pragma unroll
    for (int i = 0; i < 4; i++)
#pragma unroll
        for (int j = 0; j < 4; j++)
            g_gbuf[(size_t)(m0 + ty * 4 + i) * B_D + (n0 + tx * 4 + j)] = acc[i][j];
}

// gates + c update (+ o pre-activation)
__global__ void __launch_bounds__(256)
k_gate(const float* __restrict__ b_i, int t)
{
    int idx = blockIdx.x * 256 + threadIdx.x;     // over H*B
    int r = idx >> 8, b = idx & 255;
    const float* iit = g_ii + (size_t)t * GATE_M * B_D;
    int rb = r * B_D + b;

    float pi = iit[rb]                    + g_gbuf[rb]                    + g_gbuf[(size_t)(GATE_M + r) * B_D + b]              + b_i[r];
    float pf = iit[(size_t)(H_D + r)*B_D + b]   + g_gbuf[(size_t)(H_D + r)*B_D + b]   + g_gbuf[(size_t)(GATE_M + H_D + r)*B_D + b]   + b_i[H_D + r];
    float pz = iit[(size_t)(2*H_D + r)*B_D + b] + g_gbuf[(size_t)(2*H_D + r)*B_D + b] + g_gbuf[(size_t)(GATE_M + 2*H_D + r)*B_D + b] + b_i[2*H_D + r];

    float ig = sigm(pi), fg = sigm(pf), zg = tanhf(pz);
    float cn = fg * g_c[idx] + ig * zg;
    g_c[idx] = cn;
    g_opre[idx] = iit[(size_t)(3*H_D + r) * B_D + b] + g_gbuf[(size_t)(3*H_D + r) * B_D + b] + b_i[3*H_D + r];
}

// acc = w_co @ c_new;  o = sigm(opre + acc);  h = o * tanh(c_new)
__global__ void __launch_bounds__(256)
k_co(const float* __restrict__ w_co)
{
    __shared__ float sm[16 * 64];
    int n0 = blockIdx.x * 32, m0 = blockIdx.y * 32;
    float acc[2][2] = {};
    gemm_tile<32,32,16,2,2,false>(w_co, g_c, H_D, H_D, B_D, m0, n0, acc, sm);
    int tx = threadIdx.x % 16, ty = threadIdx.x / 16;
#pragma unroll
    for (int i = 0; i < 2; i++)
#pragma unroll
        for (int j = 0; j < 2; j++) {
            int rb = (m0 + ty * 2 + i) * B_D + (n0 + tx * 2 + j);
            float o = sigm(g_opre[rb] + acc[i][j]);
            g_h[rb] = o * tanhf(g_c[rb]);
        }
}

// T_new = w_ht @ h_new + b[4H:] + t_add[t]; stored as Ts[t] (doubles as T state)
__global__ void __launch_bounds__(256)
k_ht(const float* __restrict__ w_ht, const float* __restrict__ b_i, int t)
{
    __shared__ float sm[16 * 64];
    int n0 = blockIdx.x * 32, m0 = blockIdx.y * 32;
    float acc[2][2] = {};
    gemm_tile<32,32,16,2,2,false>(w_ht, g_h, H_D, H_D, B_D, m0, n0, acc, sm);
    int tx = threadIdx.x % 16, ty = threadIdx.x / 16;
    size_t base = (size_t)t * HB;
#pragma unroll
    for (int i = 0; i < 2; i++)
#pragma unroll
        for (int j = 0; j < 2; j++) {
            int r = m0 + ty * 2 + i, c = n0 + tx * 2 + j;
            g_Ts[base + (size_t)r * B_D + c] = acc[i][j] + b_i[4 * H_D + r] + g_tadd[base + (size_t)r * B_D + c];
        }
}

// ---------------------------------------------------------------------------
// Phase C kernels
// ---------------------------------------------------------------------------

// Tag heads + log_softmax, direct (b,t,y) layout writes
__global__ void __launch_bounds__(256)
k_y(const float* __restrict__ wyf, const float* __restrict__ byf,
    const float* __restrict__ wyc, const float* __restrict__ byc,
    float* __restrict__ out)
{
    __shared__ float sm[2 * 64 * 68];   // also used as GEMM smem (needs 2048)
    int t = blockIdx.y, n0 = blockIdx.x * 64;
    const float* Tst = g_Ts + (size_t)t * HB;
    float aF[4][4] = {}, aC[4][4] = {};
    gemm_tile<64,64,16,4,4,false>(wyf, Tst, H_D, H_D, B_D, 0, n0, aF, sm);
    gemm_tile<64,64,16,4,4,false>(wyc, Tst, H_D, H_D, B_D, 0, n0, aC, sm);

    float (*yF)[68] = (float (*)[68])sm;
    float (*yC)[68] = (float (*)[68])(sm + 64 * 68);
    int tx = threadIdx.x % 16, ty = threadIdx.x / 16;
#pragma unroll
    for (int i = 0; i < 4; i++)
#pragma unroll
        for (int j = 0; j < 4; j++) {
            int m = ty * 4 + i, n = tx * 4 + j;
            yF[m][n] = aF[i][j] + byf[m];
            yC[m][n] = aC[i][j] + byc[m];
        }
    __syncthreads();

    if (threadIdx.x < 64) {
        int col = threadIdx.x;
        int b = n0 + col;
        float mxF = -1e30f, mxC = -1e30f;
#pragma unroll
        for (int m = 0; m < TAG; m++) {
            mxF = fmaxf(mxF, yF[m][col]);
            mxC = fmaxf(mxC, yC[m][col]);
        }
        float sF = 0.f, sC = 0.f;
#pragma unroll
        for (int m = 0; m < TAG; m++) {
            sF += expf(yF[m][col] - mxF);
            sC += expf(yC[m][col] - mxC);
        }
        float lseF = mxF + logf(sF);
        float lseC = mxC + logf(sC);
        size_t base = ((size_t)b * T_STEPS + t) * TAG;
#pragma unroll
        for (int m = 0; m < TAG; m++) {
            float vf = yF[m][col], vc = yC[m][col];
            out[OFF_LF + base + m] = vf - lseF;
            out[OFF_LC + base + m] = vc - lseC;
            out[OFF_YF + base + m] = vf;
            out[OFF_YC + base + m] = vc;
        }
    }
}

// Ts (t,h,b) -> out (b,t,h) transpose
__global__ void k_tsout(float* __restrict__ out)
{
    __shared__ float tile[32][33];
    int t = blockIdx.z;
    int b0 = blockIdx.x * 32, h0 = blockIdx.y * 32;
    int tx = threadIdx.x, ty = threadIdx.y;   // 32 x 8
    size_t base = (size_t)t * HB;
    for (int i = ty; i < 32; i += 8)
        tile[i][tx] = g_Ts[base + (size_t)(h0 + i) * B_D + (b0 + tx)];
    __syncthreads();
    for (int i = ty; i < 32; i += 8)
        out[OFF_TS + ((size_t)(b0 + i) * T_STEPS + t) * H_D + (h0 + tx)] = tile[tx][i];
}

// Initialize h, c states from inputs
__global__ void k_init(const float* __restrict__ h0, const float* __restrict__ c0)
{
    int i = blockIdx.x * 256 + threadIdx.x;
    if (i < HB) { g_h[i] = h0[i]; g_c[i] = c0[i]; }
}

// ---------------------------------------------------------------------------
// Launch
// ---------------------------------------------------------------------------
extern "C" void kernel_launch(void* const* d_in, const int* in_sizes, int n_in,
                              void* d_out, int out_size)
{
    const float* inputs   = (const float*)d_in[0];
    const float* lms      = (const float*)d_in[1];
    const float* poses    = (const float*)d_in[2];
    const float* caps     = (const float*)d_in[3];
    const float* h0       = (const float*)d_in[4];
    const float* c0       = (const float*)d_in[5];
    const float* t0       = (const float*)d_in[6];
    const float* w_ii     = (const float*)d_in[7];
    const float* w_hi     = (const float*)d_in[8];
    const float* w_ti     = (const float*)d_in[9];
    const float* w_co     = (const float*)d_in[10];
    const float* w_ht     = (const float*)d_in[11];
    const float* b_i      = (const float*)d_in[12];
    const float* w_y_fact = (const float*)d_in[13];
    const float* b_y_fact = (const float*)d_in[14];
    const float* w_y_cond = (const float*)d_in[15];
    const float* b_y_cond = (const float*)d_in[16];
    const float* w_lmw    = (const float*)d_in[17];
    const float* w_posw   = (const float*)d_in[18];
    const float* w_capw   = (const float*)d_in[19];
    const float* w_lmt    = (const float*)d_in[20];
    const float* w_post   = (const float*)d_in[21];
    const float* w_capt   = (const float*)d_in[22];
    float* out = (float*)d_out;

    k_init<<<HB / 256, 256>>>(h0, c0);
    k_x   <<<dim3(B_D / 64, IN_D / 64, T_STEPS), 256>>>(inputs, lms, poses, caps, w_lmw, w_posw, w_capw);
    k_tadd<<<dim3(B_D / 64, H_D / 64, T_STEPS), 256>>>(lms, poses, caps, w_lmt, w_post, w_capt);
    k_ii  <<<dim3(B_D / 64, GATE_M / 64, T_STEPS), 256>>>(w_ii);

    for (int t = 0; t < T_STEPS; t++) {
        k_hi_ti<<<dim3(B_D / 64, GB_M / 64), 256>>>(w_hi, w_ti, t0, t);
        k_gate <<<HB / 256, 256>>>(b_i, t);
        k_co   <<<dim3(B_D / 32, H_D / 32), 256>>>(w_co);
        k_ht   <<<dim3(B_D / 32, H_D / 32), 256>>>(w_ht, b_i, t);
    }

    k_y    <<<dim3(B_D / 64, T_STEPS), 256>>>(w_y_fact, b_y_fact, w_y_cond, b_y_cond, out);
    k_tsout<<<dim3(B_D / 32, H_D / 32, T_STEPS), dim3(32, 8)>>>(out);
}

// round 3
// speedup vs baseline: 1.0045x; 1.0045x over previous
#include <cuda_runtime.h>
#include <math.h>

// ---------------------------------------------------------------------------
// Problem constants
// ---------------------------------------------------------------------------
#define T_STEPS 128
#define IN_D    512
#define H_D     512
#define B_D     256
#define TAG     64
#define LM_D    200
#define POS_D   6
#define CAP_D   3
#define HB      (H_D * B_D)          // 131072
#define GATE_M  (4 * H_D)            // 2048
#define TI_M    (3 * H_D)            // 1536
#define GB_M    (GATE_M + TI_M)      // 3584

// Output section offsets (floats) in d_out: lf, lc, y_fact, y_cond, Ts
#define SEC_Y   ((size_t)B_D * T_STEPS * TAG)       // 2,097,152
#define OFF_LF  ((size_t)0)
#define OFF_LC  (SEC_Y)
#define OFF_YF  (2 * SEC_Y)
#define OFF_YC  (3 * SEC_Y)
#define OFF_TS  (4 * SEC_Y)

// ---------------------------------------------------------------------------
// Scratch (device globals; no allocations allowed)
// ---------------------------------------------------------------------------
__device__ float g_x   [(size_t)T_STEPS * IN_D  * B_D];   //  67 MB
__device__ float g_ii  [(size_t)T_STEPS * GATE_M * B_D];  // 268 MB
__device__ float g_tadd[(size_t)T_STEPS * H_D  * B_D];    //  67 MB
__device__ float g_Ts  [(size_t)T_STEPS * H_D  * B_D];    //  67 MB
__device__ float g_gbuf[(size_t)GB_M * B_D];              // hi (2048 rows) + ti (1536 rows)
__device__ float g_c   [HB];
__device__ float g_h   [HB];
__device__ float g_opre[HB];

__device__ __forceinline__ float sigm(float x) { return 1.f / (1.f + expf(-x)); }

// ---------------------------------------------------------------------------
// Generic tiled SGEMM tile accumulator.
// C tile = A (MxK) @ B (KxN), A row-major (or transposed, AT=true: A is KxM).
// 256 threads/CTA. Thread (tx = tid%16, ty = tid/16) owns a TMxTN sub-tile.
// K is bound-checked (zero fill) so K need not be a multiple of BK.
// M tile and N tile are assumed fully in range (all our dims are multiples).
// ---------------------------------------------------------------------------
template <int BM, int BN, int BK, int TM, int TN, bool AT>
__device__ __forceinline__ void gemm_tile(const float* __restrict__ A,
                                          const float* __restrict__ B,
                                          int K, int lda, int ldb,
                                          int m0, int n0,
                                          float (&acc)[TM][TN], float* sm)
{
    static_assert((BM / TM) * (BN / TN) == 256, "256 threads required");
    float (*As)[BM] = (float (*)[BM])sm;
    float (*Bs)[BN] = (float (*)[BN])(sm + BK * BM);
    const int tid = threadIdx.x;
    const int tx  = tid % (BN / TN);
    const int ty  = tid / (BN / TN);
    constexpr int LA = (BM * BK) / 256;
    constexpr int LB = (BK * BN) / 256;

    for (int k0 = 0; k0 < K; k0 += BK) {
#pragma unroll
        for (int i = 0; i < LA; i++) {
            int li = tid + i * 256;
            if (AT) {
                int k = li / BM, m = li % BM;
                int kk = k0 + k;
                As[k][m] = (kk < K) ? A[(size_t)kk * lda + (m0 + m)] : 0.f;
            } else {
                int m = li / BK, k = li % BK;
                int kk = k0 + k;
                As[k][m] = (kk < K) ? A[(size_t)(m0 + m) * lda + kk] : 0.f;
            }
        }
#pragma unroll
        for (int i = 0; i < LB; i++) {
            int li = tid + i * 256;
            int k = li / BN, n = li % BN;
            int kk = k0 + k;
            Bs[k][n] = (kk < K) ? B[(size_t)kk * ldb + (n0 + n)] : 0.f;
        }
        __syncthreads();
#pragma unroll
        for (int k = 0; k < BK; k++) {
            float av[TM], bv[TN];
#pragma unroll
            for (int i = 0; i < TM; i++) av[i] = As[k][ty * TM + i];
#pragma unroll
            for (int j = 0; j < TN; j++) bv[j] = Bs[k][tx * TN + j];
#pragma unroll
            for (int i = 0; i < TM; i++)
#pragma unroll
                for (int j = 0; j < TN; j++) acc[i][j] += av[i] * bv[j];
        }
        __syncthreads();
    }
}

// ---------------------------------------------------------------------------
// Phase A kernels (parallel over t)
// ---------------------------------------------------------------------------

// x[t,i,b] = inputs + w_lmw^T@lm + w_posw^T@pos + w_capw^T@cap
__global__ void __launch_bounds__(256)
k_x(const float* __restrict__ inputs, const float* __restrict__ lms,
    const float* __restrict__ poses, const float* __restrict__ caps,
    const float* __restrict__ w_lmw, const float* __restrict__ w_posw,
    const float* __restrict__ w_capw)
{
    __shared__ float sm[16 * 128];
    int t = blockIdx.z, m0 = blockIdx.y * 64, n0 = blockIdx.x * 64;
    float acc[4][4] = {};
    gemm_tile<64,64,16,4,4,true>(w_lmw,  lms   + (size_t)t * LM_D  * B_D, LM_D,  IN_D, B_D, m0, n0, acc, sm);
    gemm_tile<64,64,16,4,4,true>(w_posw, poses + (size_t)t * POS_D * B_D, POS_D, IN_D, B_D, m0, n0, acc, sm);
    gemm_tile<64,64,16,4,4,true>(w_capw, caps  + (size_t)t * CAP_D * B_D, CAP_D, IN_D, B_D, m0, n0, acc, sm);
    int tx = threadIdx.x % 16, ty = threadIdx.x / 16;
    size_t base = (size_t)t * IN_D * B_D;
#pragma unroll
    for (int i = 0; i < 4; i++)
#pragma unroll
        for (int j = 0; j < 4; j++) {
            size_t idx = base + (size_t)(m0 + ty * 4 + i) * B_D + (n0 + tx * 4 + j);
            g_x[idx] = acc[i][j] + inputs[idx];
        }
}

// t_add[t,h,b] = w_lmt@lm + w_post@pos + w_capt@cap
__global__ void __launch_bounds__(256)
k_tadd(const float* __restrict__ lms, const float* __restrict__ poses,
       const float* __restrict__ caps, const float* __restrict__ w_lmt,
       const float* __restrict__ w_post, const float* __restrict__ w_capt)
{
    __shared__ float sm[16 * 128];
    int t = blockIdx.z, m0 = blockIdx.y * 64, n0 = blockIdx.x * 64;
    float acc[4][4] = {};
    gemm_tile<64,64,16,4,4,false>(w_lmt,  lms   + (size_t)t * LM_D  * B_D, LM_D,  LM_D,  B_D, m0, n0, acc, sm);
    gemm_tile<64,64,16,4,4,false>(w_post, poses + (size_t)t * POS_D * B_D, POS_D, POS_D, B_D, m0, n0, acc, sm);
    gemm_tile<64,64,16,4,4,false>(w_capt, caps  + (size_t)t * CAP_D * B_D, CAP_D, CAP_D, B_D, m0, n0, acc, sm);
    int tx = threadIdx.x % 16, ty = threadIdx.x / 16;
    size_t base = (size_t)t * H_D * B_D;
#pragma unroll
    for (int i = 0; i < 4; i++)
#pragma unroll
        for (int j = 0; j < 4; j++)
            g_tadd[base + (size_t)(m0 + ty * 4 + i) * B_D + (n0 + tx * 4 + j)] = acc[i][j];
}

// ii_all[t] = w_ii @ x[t]
__global__ void __launch_bounds__(256)
k_ii(const float* __restrict__ w_ii)
{
    __shared__ float sm[16 * 128];
    int t = blockIdx.z, m0 = blockIdx.y * 64, n0 = blockIdx.x * 64;
    float acc[4][4] = {};
    gemm_tile<64,64,16,4,4,false>(w_ii, g_x + (size_t)t * IN_D * B_D, IN_D, IN_D, B_D, m0, n0, acc, sm);
    int tx = threadIdx.x % 16, ty = threadIdx.x / 16;
    size_t base = (size_t)t * GATE_M * B_D;
#pragma unroll
    for (int i = 0; i < 4; i++)
#pragma unroll
        for (int j = 0; j < 4; j++)
            g_ii[base + (size_t)(m0 + ty * 4 + i) * B_D + (n0 + tx * 4 + j)] = acc[i][j];
}

// ---------------------------------------------------------------------------
// Recurrent step kernels
// ---------------------------------------------------------------------------

// gbuf[0:2048)   = w_hi @ h_prev
// gbuf[2048:3584) = w_ti @ T_prev
__global__ void __launch_bounds__(256)
k_hi_ti(const float* __restrict__ w_hi, const float* __restrict__ w_ti,
        const float* __restrict__ t0, int t)
{
    __shared__ float sm[16 * 128];
    int n0 = blockIdx.x * 64, m0 = blockIdx.y * 64;
    const float* Tprev = (t == 0) ? t0 : (g_Ts + (size_t)(t - 1) * HB);
    float acc[4][4] = {};
    if (m0 < GATE_M)
        gemm_tile<64,64,16,4,4,false>(w_hi, g_h,   H_D, H_D, B_D, m0,          n0, acc, sm);
    else
        gemm_tile<64,64,16,4,4,false>(w_ti, Tprev, H_D, H_D, B_D, m0 - GATE_M, n0, acc, sm);
    int tx = threadIdx.x % 16, ty = threadIdx.x / 16;
#pragma unroll
    for (int i = 0; i < 4; i++)
#pragma unroll
        for (int j = 0; j < 4; j++)
            g_gbuf[(size_t)(m0 + ty * 4 + i) * B_D + (n0 + tx * 4 + j)] = acc[i][j];
}

// gates + c update (+ o pre-activation)
__global__ void __launch_bounds__(256)
k_gate(const float* __restrict__ b_i, int t)
{
    int idx = blockIdx.x * 256 + threadIdx.x;     // over H*B
    int r = idx >> 8, b = idx & 255;
    const float* iit = g_ii + (size_t)t * GATE_M * B_D;
    int rb = r * B_D + b;

    float pi = iit[rb]                    + g_gbuf[rb]                    + g_gbuf[(size_t)(GATE_M + r) * B_D + b]              + b_i[r];
    float pf = iit[(size_t)(H_D + r)*B_D + b]   + g_gbuf[(size_t)(H_D + r)*B_D + b]   + g_gbuf[(size_t)(GATE_M + H_D + r)*B_D + b]   + b_i[H_D + r];
    float pz = iit[(size_t)(2*H_D + r)*B_D + b] + g_gbuf[(size_t)(2*H_D + r)*B_D + b] + g_gbuf[(size_t)(GATE_M + 2*H_D + r)*B_D + b] + b_i[2*H_D + r];

    float ig = sigm(pi), fg = sigm(pf), zg = tanhf(pz);
    float cn = fg * g_c[idx] + ig * zg;
    g_c[idx] = cn;
    g_opre[idx] = iit[(size_t)(3*H_D + r) * B_D + b] + g_gbuf[(size_t)(3*H_D + r) * B_D + b] + b_i[3*H_D + r];
}

// acc = w_co @ c_new;  o = sigm(opre + acc);  h = o * tanh(c_new)
__global__ void __launch_bounds__(256)
k_co(const float* __restrict__ w_co)
{
    __shared__ float sm[16 * 64];
    int n0 = blockIdx.x * 32, m0 = blockIdx.y * 32;
    float acc[2][2] = {};
    gemm_tile<32,32,16,2,2,false>(w_co, g_c, H_D, H_D, B_D, m0, n0, acc, sm);
    int tx = threadIdx.x % 16, ty = threadIdx.x / 16;
#pragma unroll
    for (int i = 0; i < 2; i++)
#pragma unroll
        for (int j = 0; j < 2; j++) {
            int rb = (m0 + ty * 2 + i) * B_D + (n0 + tx * 2 + j);
            float o = sigm(g_opre[rb] + acc[i][j]);
            g_h[rb] = o * tanhf(g_c[rb]);
        }
}

// T_new = w_ht @ h_new + b[4H:] + t_add[t]; stored as Ts[t] (doubles as T state)
__global__ void __launch_bounds__(256)
k_ht(const float* __restrict__ w_ht, const float* __restrict__ b_i, int t)
{
    __shared__ float sm[16 * 64];
    int n0 = blockIdx.x * 32, m0 = blockIdx.y * 32;
    float acc[2][2] = {};
    gemm_tile<32,32,16,2,2,false>(w_ht, g_h, H_D, H_D, B_D, m0, n0, acc, sm);
    int tx = threadIdx.x % 16, ty = threadIdx.x / 16;
    size_t base = (size_t)t * HB;
#pragma unroll
    for (int i = 0; i < 2; i++)
#pragma unroll
        for (int j = 0; j < 2; j++) {
            int r = m0 + ty * 2 + i, c = n0 + tx * 2 + j;
            g_Ts[base + (size_t)r * B_D + c] = acc[i][j] + b_i[4 * H_D + r] + g_tadd[base + (size_t)r * B_D + c];
        }
}

// ---------------------------------------------------------------------------
// Phase C kernels
// ---------------------------------------------------------------------------

// Tag heads + log_softmax, direct (b,t,y) layout writes
__global__ void __launch_bounds__(256)
k_y(const float* __restrict__ wyf, const float* __restrict__ byf,
    const float* __restrict__ wyc, const float* __restrict__ byc,
    float* __restrict__ out)
{
    __shared__ float sm[2 * 64 * 68];   // also used as GEMM smem (needs 2048)
    int t = blockIdx.y, n0 = blockIdx.x * 64;
    const float* Tst = g_Ts + (size_t)t * HB;
    float aF[4][4] = {}, aC[4][4] = {};
    gemm_tile<64,64,16,4,4,false>(wyf, Tst, H_D, H_D, B_D, 0, n0, aF, sm);
    gemm_tile<64,64,16,4,4,false>(wyc, Tst, H_D, H_D, B_D, 0, n0, aC, sm);

    float (*yF)[68] = (float (*)[68])sm;
    float (*yC)[68] = (float (*)[68])(sm + 64 * 68);
    int tx = threadIdx.x % 16, ty = threadIdx.x / 16;
#pragma unroll
    for (int i = 0; i < 4; i++)
#pragma unroll
        for (int j = 0; j < 4; j++) {
            int m = ty * 4 + i, n = tx * 4 + j;
            yF[m][n] = aF[i][j] + byf[m];
            yC[m][n] = aC[i][j] + byc[m];
        }
    __syncthreads();

    if (threadIdx.x < 64) {
        int col = threadIdx.x;
        int b = n0 + col;
        float mxF = -1e30f, mxC = -1e30f;
#pragma unroll
        for (int m = 0; m < TAG; m++) {
            mxF = fmaxf(mxF, yF[m][col]);
            mxC = fmaxf(mxC, yC[m][col]);
        }
        float sF = 0.f, sC = 0.f;
#pragma unroll
        for (int m = 0; m < TAG; m++) {
            sF += expf(yF[m][col] - mxF);
            sC += expf(yC[m][col] - mxC);
        }
        float lseF = mxF + logf(sF);
        float lseC = mxC + logf(sC);
        size_t base = ((size_t)b * T_STEPS + t) * TAG;
#pragma unroll
        for (int m = 0; m < TAG; m++) {
            float vf = yF[m][col], vc = yC[m][col];
            out[OFF_LF + base + m] = vf - lseF;
            out[OFF_LC + base + m] = vc - lseC;
            out[OFF_YF + base + m] = vf;
            out[OFF_YC + base + m] = vc;
        }
    }
}

// Ts (t,h,b) -> out (b,t,h) transpose
__global__ void k_tsout(float* __restrict__ out)
{
    __shared__ float tile[32][33];
    int t = blockIdx.z;
    int b0 = blockIdx.x * 32, h0 = blockIdx.y * 32;
    int tx = threadIdx.x, ty = threadIdx.y;   // 32 x 8
    size_t base = (size_t)t * HB;
    for (int i = ty; i < 32; i += 8)
        tile[i][tx] = g_Ts[base + (size_t)(h0 + i) * B_D + (b0 + tx)];
    __syncthreads();
    for (int i = ty; i < 32; i += 8)
        out[OFF_TS + ((size_t)(b0 + i) * T_STEPS + t) * H_D + (h0 + tx)] = tile[tx][i];
}

// Initialize h, c states from inputs
__global__ void k_init(const float* __restrict__ h0, const float* __restrict__ c0)
{
    int i = blockIdx.x * 256 + threadIdx.x;
    if (i < HB) { g_h[i] = h0[i]; g_c[i] = c0[i]; }
}

// ---------------------------------------------------------------------------
// Launch
// ---------------------------------------------------------------------------
extern "C" void kernel_launch(void* const* d_in, const int* in_sizes, int n_in,
                              void* d_out, int out_size)
{
    const float* inputs   = (const float*)d_in[0];
    const float* lms      = (const float*)d_in[1];
    const float* poses    = (const float*)d_in[2];
    const float* caps     = (const float*)d_in[3];
    const float* h0       = (const float*)d_in[4];
    const float* c0       = (const float*)d_in[5];
    const float* t0       = (const float*)d_in[6];
    const float* w_ii     = (const float*)d_in[7];
    const float* w_hi     = (const float*)d_in[8];
    const float* w_ti     = (const float*)d_in[9];
    const float* w_co     = (const float*)d_in[10];
    const float* w_ht     = (const float*)d_in[11];
    const float* b_i      = (const float*)d_in[12];
    const float* w_y_fact = (const float*)d_in[13];
    const float* b_y_fact = (const float*)d_in[14];
    const float* w_y_cond = (const float*)d_in[15];
    const float* b_y_cond = (const float*)d_in[16];
    const float* w_lmw    = (const float*)d_in[17];
    const float* w_posw   = (const float*)d_in[18];
    const float* w_capw   = (const float*)d_in[19];
    const float* w_lmt    = (const float*)d_in[20];
    const float* w_post   = (const float*)d_in[21];
    const float* w_capt   = (const float*)d_in[22];
    float* out = (float*)d_out;

    k_init<<<HB / 256, 256>>>(h0, c0);
    k_x   <<<dim3(B_D / 64, IN_D / 64, T_STEPS), 256>>>(inputs, lms, poses, caps, w_lmw, w_posw, w_capw);
    k_tadd<<<dim3(B_D / 64, H_D / 64, T_STEPS), 256>>>(lms, poses, caps, w_lmt, w_post, w_capt);
    k_ii  <<<dim3(B_D / 64, GATE_M / 64, T_STEPS), 256>>>(w_ii);

    for (int t = 0; t < T_STEPS; t++) {
        k_hi_ti<<<dim3(B_D / 64, GB_M / 64), 256>>>(w_hi, w_ti, t0, t);
        k_gate <<<HB / 256, 256>>>(b_i, t);
        k_co   <<<dim3(B_D / 32, H_D / 32), 256>>>(w_co);
        k_ht   <<<dim3(B_D / 32, H_D / 32), 256>>>(w_ht, b_i, t);
    }

    k_y    <<<dim3(B_D / 64, T_STEPS), 256>>>(w_y_fact, b_y_fact, w_y_cond, b_y_cond, out);
    k_tsout<<<dim3(B_D / 32, H_D / 32, T_STEPS), dim3(32, 8)>>>(out);
}

// round 4
// speedup vs baseline: 1.2150x; 1.2095x over previous
#include <cuda_runtime.h>
#include <math.h>

#define T_STEPS 128
#define IN_D    512
#define H_D     512
#define B_D     256
#define TAG     64
#define LM_D    200
#define POS_D   6
#define CAP_D   3
#define HB      (H_D * B_D)
#define GATE_M  (4 * H_D)            // 2048
#define TI_M    (3 * H_D)            // 1536

#define SEC_Y   ((size_t)B_D * T_STEPS * TAG)
#define OFF_LF  ((size_t)0)
#define OFF_LC  (SEC_Y)
#define OFF_YF  (2 * SEC_Y)
#define OFF_YC  (3 * SEC_Y)
#define OFF_TS  (4 * SEC_Y)

// ------------------------- scratch (device globals) -------------------------
__device__ float g_x    [(size_t)T_STEPS * IN_D   * B_D];
__device__ float g_pre  [(size_t)T_STEPS * GATE_M * B_D];  // permuted 4r+g: ii+tiC+b
__device__ float g_tiC  [(size_t)T_STEPS * TI_M   * B_D];
__device__ float g_tadd [(size_t)T_STEPS * H_D    * B_D];
__device__ float g_hall [(size_t)T_STEPS * H_D    * B_D];
__device__ float g_Ts   [(size_t)T_STEPS * H_D    * B_D];
__device__ float g_c    [HB];
__device__ float g_opre [HB];
// k-major weights
__device__ float g_wfT  [(size_t)H_D * GATE_M];   // folded, permuted
__device__ float g_wiiT [(size_t)IN_D * GATE_M];  // permuted
__device__ float g_wtiT [(size_t)H_D * TI_M];
__device__ float g_whtT [(size_t)H_D * H_D];
__device__ float g_wcoT [(size_t)H_D * H_D];
__device__ float g_wlmtT[(size_t)LM_D * H_D];
__device__ float g_wpostT[(size_t)POS_D * H_D];
__device__ float g_wcaptT[(size_t)CAP_D * H_D];
__device__ float g_wyfT [(size_t)H_D * TAG];
__device__ float g_wycT [(size_t)H_D * TAG];
__device__ float g_AlmT [(size_t)LM_D * TI_M];    // (w_ti@w_lmt)^T
__device__ float g_AposT[(size_t)POS_D * TI_M];
__device__ float g_AcapT[(size_t)CAP_D * TI_M];
__device__ float g_vc   [TI_M];                   // w_ti @ b5

__device__ __forceinline__ float sigm(float x) { return 1.f / (1.f + expf(-x)); }

// ---------------------------------------------------------------------------
// GEMM core. A k-major (A[k][m], ld ldA), B k-major (B[k][n], ld ldB).
// 256 threads; thread (tx,ty) owns TMxTN. K row-guarded (zero fill).
// ---------------------------------------------------------------------------
template <int BM, int BN, int BK, int TM, int TN>
__device__ __forceinline__ void gk(const float* __restrict__ A,
                                   const float* __restrict__ B,
                                   int K, int ldA, int ldB, int m0, int n0,
                                   float (&acc)[TM][TN], float* sm)
{
    static_assert((BM / TM) * (BN / TN) == 256, "");
    static_assert((BM * BK / 4) % 256 == 0 && (BN * BK / 4) % 256 == 0, "");
    float (*As)[BM] = (float (*)[BM])sm;
    float (*Bs)[BN] = (float (*)[BN])(sm + BK * BM);
    const int tid = threadIdx.x;
    const int tx = tid % (BN / TN), ty = tid / (BN / TN);
    constexpr int AV = BM / 4, BV = BN / 4;
    constexpr int AL = (BM * BK / 4) / 256, BL = (BN * BK / 4) / 256;
    const float4 z4 = make_float4(0.f, 0.f, 0.f, 0.f);

    for (int k0 = 0; k0 < K; k0 += BK) {
#pragma unroll
        for (int i = 0; i < AL; i++) {
            int li = tid + i * 256, k = li / AV, m4 = (li % AV) * 4;
            float4 v = (k0 + k < K) ? *(const float4*)&A[(size_t)(k0 + k) * ldA + m0 + m4] : z4;
            *(float4*)&As[k][m4] = v;
        }
#pragma unroll
        for (int i = 0; i < BL; i++) {
            int li = tid + i * 256, k = li / BV, n4 = (li % BV) * 4;
            float4 v = (k0 + k < K) ? *(const float4*)&B[(size_t)(k0 + k) * ldB + n0 + n4] : z4;
            *(float4*)&Bs[k][n4] = v;
        }
        __syncthreads();
#pragma unroll
        for (int k = 0; k < BK; k++) {
            float a[TM], b[TN];
            if constexpr (TM % 4 == 0) {
#pragma unroll
                for (int i = 0; i < TM; i += 4) {
                    float4 v = *(const float4*)&As[k][ty * TM + i];
                    a[i] = v.x; a[i+1] = v.y; a[i+2] = v.z; a[i+3] = v.w;
                }
            } else {
                float2 v = *(const float2*)&As[k][ty * TM];
                a[0] = v.x; a[1] = v.y;
            }
            if constexpr (TN == 4) {
                float4 v = *(const float4*)&Bs[k][tx * 4];
                b[0] = v.x; b[1] = v.y; b[2] = v.z; b[3] = v.w;
            } else {
                float2 v = *(const float2*)&Bs[k][tx * 2];
                b[0] = v.x; b[1] = v.y;
            }
#pragma unroll
            for (int i = 0; i < TM; i++)
#pragma unroll
                for (int j = 0; j < TN; j++) acc[i][j] += a[i] * b[j];
        }
        __syncthreads();
    }
}

// --------------------------- one-time precompute ---------------------------
// out[k*M+m] = in[m*K+k]
__global__ void k_tr(const float* __restrict__ in, float* __restrict__ out, int M, int K)
{
    __shared__ float tl[32][33];
    int k0 = blockIdx.x * 32, m0 = blockIdx.y * 32;
    int tx = threadIdx.x, ty = threadIdx.y;
    for (int i = ty; i < 32; i += 8)
        if (m0 + i < M && k0 + tx < K) tl[i][tx] = in[(size_t)(m0 + i) * K + k0 + tx];
    __syncthreads();
    for (int i = ty; i < 32; i += 8)
        if (k0 + i < K && m0 + tx < M) out[(size_t)(k0 + i) * M + m0 + tx] = tl[tx][i];
}

// g_wiiT[k][p] = w_ii[m(p)][k],  m(p) = (p&3)*512 + (p>>2)
__global__ void k_permii(const float* __restrict__ w_ii)
{
    __shared__ float tl[32][33];
    int p0 = blockIdx.x * 32, k0 = blockIdx.y * 32;
    int tx = threadIdx.x, ty = threadIdx.y;
    for (int i = ty; i < 32; i += 8) {
        int p = p0 + i, m = (p & 3) * H_D + (p >> 2);
        tl[i][tx] = w_ii[(size_t)m * IN_D + k0 + tx];
    }
    __syncthreads();
    for (int i = ty; i < 32; i += 8)
        g_wiiT[(size_t)(k0 + i) * GATE_M + p0 + tx] = tl[tx][i];
}

// g_wfT[j][4r+g] = (w_ti@w_ht)[g*512+r][j] + w_hi[g*512+r][j], g<3
__global__ void __launch_bounds__(256)
k_w2(const float* __restrict__ w_hi, const float* __restrict__ w_ht)
{
    __shared__ float sm[16 * 128];
    int n0 = blockIdx.x * 64, m0 = blockIdx.y * 64;
    float acc[4][4] = {};
    gk<64,64,16,4,4>(g_wtiT, w_ht, H_D, TI_M, H_D, m0, n0, acc, sm);
    int tx = threadIdx.x % 16, ty = threadIdx.x / 16;
#pragma unroll
    for (int i = 0; i < 4; i++) {
        int m = m0 + ty * 4 + i;               // g-major row in [0,1536)
        int p = (m & 511) * 4 + (m >> 9);
#pragma unroll
        for (int j = 0; j < 4; j++) {
            int jc = n0 + tx * 4 + j;
            g_wfT[(size_t)jc * GATE_M + p] = acc[i][j] + w_hi[(size_t)m * H_D + jc];
        }
    }
}

__global__ void k_fillo(const float* __restrict__ w_hi)
{
    int idx = blockIdx.x * 256 + threadIdx.x;
    if (idx >= H_D * H_D) return;
    int r = idx >> 9, j = idx & 511;
    g_wfT[(size_t)j * GATE_M + 4 * r + 3] = w_hi[(size_t)(3 * H_D + r) * H_D + j];
}

// A_lm/A_pos/A_cap (transposed) and v_c
__global__ void k_small(const float* __restrict__ w_lmt, const float* __restrict__ w_post,
                        const float* __restrict__ w_capt, const float* __restrict__ b_i)
{
    int idx = blockIdx.x * 256 + threadIdx.x;
    if (idx < TI_M * LM_D) {
        int l = idx / TI_M, m = idx % TI_M;
        float s = 0.f;
        for (int k = 0; k < H_D; k++) s += g_wtiT[(size_t)k * TI_M + m] * w_lmt[k * LM_D + l];
        g_AlmT[(size_t)l * TI_M + m] = s;
    } else if (idx < TI_M * (LM_D + POS_D)) {
        int q = idx - TI_M * LM_D, l = q / TI_M, m = q % TI_M;
        float s = 0.f;
        for (int k = 0; k < H_D; k++) s += g_wtiT[(size_t)k * TI_M + m] * w_post[k * POS_D + l];
        g_AposT[(size_t)l * TI_M + m] = s;
    } else if (idx < TI_M * (LM_D + POS_D + CAP_D)) {
        int q = idx - TI_M * (LM_D + POS_D), l = q / TI_M, m = q % TI_M;
        float s = 0.f;
        for (int k = 0; k < H_D; k++) s += g_wtiT[(size_t)k * TI_M + m] * w_capt[k * CAP_D + l];
        g_AcapT[(size_t)l * TI_M + m] = s;
    } else if (idx < TI_M * (LM_D + POS_D + CAP_D + 1)) {
        int m = idx - TI_M * (LM_D + POS_D + CAP_D);
        float s = 0.f;
        for (int k = 0; k < H_D; k++) s += g_wtiT[(size_t)k * TI_M + m] * b_i[4 * H_D + k];
        g_vc[m] = s;
    }
}

__global__ void k_init(const float* __restrict__ c0)
{
    int i = blockIdx.x * 256 + threadIdx.x;
    if (i < HB) g_c[i] = c0[i];
}

// ------------------------------ phase A ------------------------------------
// x[t] = inputs[t] + w_lmw^T@lm + w_posw^T@pos + w_capw^T@cap (all A's k-major already)
__global__ void __launch_bounds__(256)
k_x(const float* __restrict__ inputs, const float* __restrict__ lms,
    const float* __restrict__ poses, const float* __restrict__ caps,
    const float* __restrict__ w_lmw, const float* __restrict__ w_posw,
    const float* __restrict__ w_capw)
{
    __shared__ float sm[16 * 128];
    int t = blockIdx.z, m0 = blockIdx.y * 64, n0 = blockIdx.x * 64;
    float acc[4][4] = {};
    gk<64,64,16,4,4>(w_lmw,  lms   + (size_t)t * LM_D  * B_D, LM_D,  IN_D, B_D, m0, n0, acc, sm);
    gk<64,64,16,4,4>(w_posw, poses + (size_t)t * POS_D * B_D, POS_D, IN_D, B_D, m0, n0, acc, sm);
    gk<64,64,16,4,4>(w_capw, caps  + (size_t)t * CAP_D * B_D, CAP_D, IN_D, B_D, m0, n0, acc, sm);
    int tx = threadIdx.x % 16, ty = threadIdx.x / 16;
    size_t base = (size_t)t * IN_D * B_D;
#pragma unroll
    for (int i = 0; i < 4; i++) {
        size_t idx = base + (size_t)(m0 + ty * 4 + i) * B_D + n0 + tx * 4;
        float4 v = *(float4*)&inputs[idx];
        float4 w = make_float4(acc[i][0] + v.x, acc[i][1] + v.y, acc[i][2] + v.z, acc[i][3] + v.w);
        *(float4*)&g_x[idx] = w;
    }
}

// tadd[t] (needed for Ts outputs)
__global__ void __launch_bounds__(256)
k_tadd(const float* __restrict__ lms, const float* __restrict__ poses,
       const float* __restrict__ caps)
{
    __shared__ float sm[16 * 128];
    int t = blockIdx.z, m0 = blockIdx.y * 64, n0 = blockIdx.x * 64;
    float acc[4][4] = {};
    gk<64,64,16,4,4>(g_wlmtT,  lms   + (size_t)t * LM_D  * B_D, LM_D,  H_D, B_D, m0, n0, acc, sm);
    gk<64,64,16,4,4>(g_wpostT, poses + (size_t)t * POS_D * B_D, POS_D, H_D, B_D, m0, n0, acc, sm);
    gk<64,64,16,4,4>(g_wcaptT, caps  + (size_t)t * CAP_D * B_D, CAP_D, H_D, B_D, m0, n0, acc, sm);
    int tx = threadIdx.x % 16, ty = threadIdx.x / 16;
    size_t base = (size_t)t * HB;
#pragma unroll
    for (int i = 0; i < 4; i++)
        *(float4*)&g_tadd[base + (size_t)(m0 + ty * 4 + i) * B_D + n0 + tx * 4] =
            make_float4(acc[i][0], acc[i][1], acc[i][2], acc[i][3]);
}

// tiC[t] = A_lm@lm[t-1]+A_pos@pos[t-1]+A_cap@cap[t-1]+v_c  (t>=1);  w_ti@t0 (t=0)
__global__ void __launch_bounds__(256)
k_tiC(const float* __restrict__ lms, const float* __restrict__ poses,
      const float* __restrict__ caps, const float* __restrict__ t0)
{
    __shared__ float sm[16 * 192];
    int t = blockIdx.z, m0 = blockIdx.y * 128, n0 = blockIdx.x * 64;
    float acc[8][4] = {};
    if (t == 0) {
        gk<128,64,16,8,4>(g_wtiT, t0, H_D, TI_M, B_D, m0, n0, acc, sm);
    } else {
        gk<128,64,16,8,4>(g_AlmT,  lms   + (size_t)(t-1) * LM_D  * B_D, LM_D,  TI_M, B_D, m0, n0, acc, sm);
        gk<128,64,16,8,4>(g_AposT, poses + (size_t)(t-1) * POS_D * B_D, POS_D, TI_M, B_D, m0, n0, acc, sm);
        gk<128,64,16,8,4>(g_AcapT, caps  + (size_t)(t-1) * CAP_D * B_D, CAP_D, TI_M, B_D, m0, n0, acc, sm);
    }
    int tx = threadIdx.x % 16, ty = threadIdx.x / 16;
    size_t base = (size_t)t * TI_M * B_D;
#pragma unroll
    for (int i = 0; i < 8; i++) {
        int m = m0 + ty * 8 + i;
        float vc = (t == 0) ? 0.f : g_vc[m];
        *(float4*)&g_tiC[base + (size_t)m * B_D + n0 + tx * 4] =
            make_float4(acc[i][0] + vc, acc[i][1] + vc, acc[i][2] + vc, acc[i][3] + vc);
    }
}

// g_pre[t][4r+g] = (w_ii@x)[g*512+r] + tiC[t][g*512+r] (g<3) + b_i[g*512+r]
__global__ void __launch_bounds__(256)
k_ii(const float* __restrict__ b_i)
{
    __shared__ float sm[16 * 192];
    int t = blockIdx.z, m0 = blockIdx.y * 128, n0 = blockIdx.x * 64;
    float acc[8][4] = {};
    gk<128,64,16,8,4>(g_wiiT, g_x + (size_t)t * IN_D * B_D, IN_D, GATE_M, B_D, m0, n0, acc, sm);
    int tx = threadIdx.x % 16, ty = threadIdx.x / 16;
    size_t base = (size_t)t * GATE_M * B_D;
    size_t tib  = (size_t)t * TI_M * B_D;
#pragma unroll
    for (int i = 0; i < 8; i++) {
        int m = m0 + ty * 8 + i;            // permuted 4r+g
        int g = m & 3, r = m >> 2;
        float bb = b_i[g * H_D + r];
        float4 tc = make_float4(0.f, 0.f, 0.f, 0.f);
        if (g < 3) tc = *(const float4*)&g_tiC[tib + (size_t)(g * H_D + r) * B_D + n0 + tx * 4];
        *(float4*)&g_pre[base + (size_t)m * B_D + n0 + tx * 4] =
            make_float4(acc[i][0] + tc.x + bb, acc[i][1] + tc.y + bb,
                        acc[i][2] + tc.z + bb, acc[i][3] + tc.w + bb);
    }
}

// ------------------------------ serial loop --------------------------------
// G = Wf@h_prev; fused gates: c_new, opre
__global__ void __launch_bounds__(256)
kA(const float* __restrict__ hprev, int t)
{
    __shared__ float sm[16 * 128];
    int m0 = blockIdx.y * 64, n0 = blockIdx.x * 64;
    float acc[4][4] = {};
    gk<64,64,16,4,4>(g_wfT, hprev, H_D, GATE_M, B_D, m0, n0, acc, sm);
    int tx = threadIdx.x % 16, ty = threadIdx.x / 16;
    int r = (m0 + ty * 4) >> 2;
    int col = n0 + tx * 4;
    size_t base = (size_t)t * GATE_M * B_D + (size_t)(m0 + ty * 4) * B_D + col;
    float4 pi = *(const float4*)&g_pre[base];
    float4 pf = *(const float4*)&g_pre[base + B_D];
    float4 pz = *(const float4*)&g_pre[base + 2 * B_D];
    float4 po = *(const float4*)&g_pre[base + 3 * B_D];
    float4 co = *(const float4*)&g_c[r * B_D + col];
    float cn[4], op[4];
    float pia[4] = {pi.x, pi.y, pi.z, pi.w}, pfa[4] = {pf.x, pf.y, pf.z, pf.w};
    float pza[4] = {pz.x, pz.y, pz.z, pz.w}, poa[4] = {po.x, po.y, po.z, po.w};
    float coa[4] = {co.x, co.y, co.z, co.w};
#pragma unroll
    for (int j = 0; j < 4; j++) {
        float ig = sigm(acc[0][j] + pia[j]);
        float fg = sigm(acc[1][j] + pfa[j]);
        float zg = tanhf(acc[2][j] + pza[j]);
        cn[j] = fg * coa[j] + ig * zg;
        op[j] = acc[3][j] + poa[j];
    }
    *(float4*)&g_c[r * B_D + col]    = make_float4(cn[0], cn[1], cn[2], cn[3]);
    *(float4*)&g_opre[r * B_D + col] = make_float4(op[0], op[1], op[2], op[3]);
}

// o = sigm(opre + w_co@c_new); h = o * tanh(c_new) -> g_hall[t]
__global__ void __launch_bounds__(256)
kB(int t)
{
    __shared__ float sm[32 * 64];
    int m0 = blockIdx.y * 32, n0 = blockIdx.x * 32;
    float acc[2][2] = {};
    gk<32,32,32,2,2>(g_wcoT, g_c, H_D, H_D, B_D, m0, n0, acc, sm);
    int tx = threadIdx.x % 16, ty = threadIdx.x / 16;
    size_t hb = (size_t)t * HB;
#pragma unroll
    for (int i = 0; i < 2; i++)
#pragma unroll
        for (int j = 0; j < 2; j++) {
            int rb = (m0 + ty * 2 + i) * B_D + n0 + tx * 2 + j;
            float o = sigm(acc[i][j] + g_opre[rb]);
            g_hall[hb + rb] = o * tanhf(g_c[rb]);
        }
}

// ------------------------------ phase C ------------------------------------
// Ts[t] = w_ht@h[t] + b5 + tadd[t]; also writes out Ts in (b,t,h)
__global__ void __launch_bounds__(256)
k_Ts(const float* __restrict__ b_i, float* __restrict__ out)
{
    __shared__ float sm[16 * 128];
    int t = blockIdx.z, m0 = blockIdx.y * 64, n0 = blockIdx.x * 64;
    float acc[4][4] = {};
    gk<64,64,16,4,4>(g_whtT, g_hall + (size_t)t * HB, H_D, H_D, B_D, m0, n0, acc, sm);
    int tx = threadIdx.x % 16, ty = threadIdx.x / 16;
    size_t base = (size_t)t * HB;
    float v[4][4];
#pragma unroll
    for (int i = 0; i < 4; i++) {
        int h = m0 + ty * 4 + i;
        float bb = b_i[4 * H_D + h];
        float4 ta = *(const float4*)&g_tadd[base + (size_t)h * B_D + n0 + tx * 4];
        v[i][0] = acc[i][0] + bb + ta.x; v[i][1] = acc[i][1] + bb + ta.y;
        v[i][2] = acc[i][2] + bb + ta.z; v[i][3] = acc[i][3] + bb + ta.w;
        *(float4*)&g_Ts[base + (size_t)h * B_D + n0 + tx * 4] =
            make_float4(v[i][0], v[i][1], v[i][2], v[i][3]);
    }
#pragma unroll
    for (int j = 0; j < 4; j++) {
        int b = n0 + tx * 4 + j;
        *(float4*)&out[OFF_TS + ((size_t)b * T_STEPS + t) * H_D + m0 + ty * 4] =
            make_float4(v[0][j], v[1][j], v[2][j], v[3][j]);
    }
}

// tag heads + log_softmax, direct (b,t,y) writes
__global__ void __launch_bounds__(256)
k_y(const float* __restrict__ byf, const float* __restrict__ byc, float* __restrict__ out)
{
    __shared__ float sm[2 * 64 * 68];
    int t = blockIdx.y, n0 = blockIdx.x * 64;
    const float* Tst = g_Ts + (size_t)t * HB;
    float aF[4][4] = {}, aC[4][4] = {};
    gk<64,64,16,4,4>(g_wyfT, Tst, H_D, TAG, B_D, 0, n0, aF, sm);
    gk<64,64,16,4,4>(g_wycT, Tst, H_D, TAG, B_D, 0, n0, aC, sm);
    float (*yF)[68] = (float (*)[68])sm;
    float (*yC)[68] = (float (*)[68])(sm + 64 * 68);
    int tx = threadIdx.x % 16, ty = threadIdx.x / 16;
#pragma unroll
    for (int i = 0; i < 4; i++)
#pragma unroll
        for (int j = 0; j < 4; j++) {
            int m = ty * 4 + i, n = tx * 4 + j;
            yF[m][n] = aF[i][j] + byf[m];
            yC[m][n] = aC[i][j] + byc[m];
        }
    __syncthreads();
    if (threadIdx.x < 64) {
        int col = threadIdx.x, b = n0 + col;
        float mxF = -1e30f, mxC = -1e30f;
#pragma unroll
        for (int m = 0; m < TAG; m++) {
            mxF = fmaxf(mxF, yF[m][col]);
            mxC = fmaxf(mxC, yC[m][col]);
        }
        float sF = 0.f, sC = 0.f;
#pragma unroll
        for (int m = 0; m < TAG; m++) {
            sF += expf(yF[m][col] - mxF);
            sC += expf(yC[m][col] - mxC);
        }
        float lseF = mxF + logf(sF), lseC = mxC + logf(sC);
        size_t base = ((size_t)b * T_STEPS + t) * TAG;
#pragma unroll
        for (int m = 0; m < TAG; m++) {
            float vf = yF[m][col], vc = yC[m][col];
            out[OFF_LF + base + m] = vf - lseF;
            out[OFF_LC + base + m] = vc - lseC;
            out[OFF_YF + base + m] = vf;
            out[OFF_YC + base + m] = vc;
        }
    }
}

// ------------------------------- launch ------------------------------------
extern "C" void kernel_launch(void* const* d_in, const int* in_sizes, int n_in,
                              void* d_out, int out_size)
{
    const float* inputs   = (const float*)d_in[0];
    const float* lms      = (const float*)d_in[1];
    const float* poses    = (const float*)d_in[2];
    const float* caps     = (const float*)d_in[3];
    const float* h0       = (const float*)d_in[4];
    const float* c0       = (const float*)d_in[5];
    const float* t0       = (const float*)d_in[6];
    const float* w_ii     = (const float*)d_in[7];
    const float* w_hi     = (const float*)d_in[8];
    const float* w_ti     = (const float*)d_in[9];
    const float* w_co     = (const float*)d_in[10];
    const float* w_ht     = (const float*)d_in[11];
    const float* b_i      = (const float*)d_in[12];
    const float* w_y_fact = (const float*)d_in[13];
    const float* b_y_fact = (const float*)d_in[14];
    const float* w_y_cond = (const float*)d_in[15];
    const float* b_y_cond = (const float*)d_in[16];
    const float* w_lmw    = (const float*)d_in[17];
    const float* w_posw   = (const float*)d_in[18];
    const float* w_capw   = (const float*)d_in[19];
    const float* w_lmt    = (const float*)d_in[20];
    const float* w_post   = (const float*)d_in[21];
    const float* w_capt   = (const float*)d_in[22];
    float* out = (float*)d_out;

    float* p;
    dim3 tb(32, 8);
    cudaGetSymbolAddress((void**)&p, g_wtiT);
    k_tr<<<dim3(16, 48), tb>>>(w_ti, p, TI_M, H_D);
    cudaGetSymbolAddress((void**)&p, g_whtT);
    k_tr<<<dim3(16, 16), tb>>>(w_ht, p, H_D, H_D);
    cudaGetSymbolAddress((void**)&p, g_wcoT);
    k_tr<<<dim3(16, 16), tb>>>(w_co, p, H_D, H_D);
    cudaGetSymbolAddress((void**)&p, g_wlmtT);
    k_tr<<<dim3(7, 16), tb>>>(w_lmt, p, H_D, LM_D);
    cudaGetSymbolAddress((void**)&p, g_wpostT);
    k_tr<<<dim3(1, 16), tb>>>(w_post, p, H_D, POS_D);
    cudaGetSymbolAddress((void**)&p, g_wcaptT);
    k_tr<<<dim3(1, 16), tb>>>(w_capt, p, H_D, CAP_D);
    cudaGetSymbolAddress((void**)&p, g_wyfT);
    k_tr<<<dim3(16, 2), tb>>>(w_y_fact, p, TAG, H_D);
    cudaGetSymbolAddress((void**)&p, g_wycT);
    k_tr<<<dim3(16, 2), tb>>>(w_y_cond, p, TAG, H_D);

    k_permii<<<dim3(64, 16), tb>>>(w_ii);
    k_w2    <<<dim3(8, 24), 256>>>(w_hi, w_ht);
    k_fillo <<<1024, 256>>>(w_hi);
    k_small <<<(TI_M * (LM_D + POS_D + CAP_D + 1) + 255) / 256, 256>>>(w_lmt, w_post, w_capt, b_i);
    k_init  <<<HB / 256, 256>>>(c0);

    k_x   <<<dim3(4, 8, T_STEPS), 256>>>(inputs, lms, poses, caps, w_lmw, w_posw, w_capw);
    k_tiC <<<dim3(4, 12, T_STEPS), 256>>>(lms, poses, caps, t0);
    k_ii  <<<dim3(4, 16, T_STEPS), 256>>>(b_i);
    k_tadd<<<dim3(4, 8, T_STEPS), 256>>>(lms, poses, caps);

    float* hall;
    cudaGetSymbolAddress((void**)&hall, g_hall);
    for (int t = 0; t < T_STEPS; t++) {
        const float* hp = (t == 0) ? h0 : (hall + (size_t)(t - 1) * HB);
        kA<<<dim3(4, 32), 256>>>(hp, t);
        kB<<<dim3(8, 16), 256>>>(t);
    }

    k_Ts<<<dim3(4, 8, T_STEPS), 256>>>(b_i, out);
    k_y <<<dim3(4, T_STEPS), 256>>>(b_y_fact, b_y_cond, out);
}

// round 5
// speedup vs baseline: 1.8657x; 1.5356x over previous
#include <cuda_runtime.h>
#include <math.h>

#define T_STEPS 128
#define IN_D    512
#define H_D     512
#define B_D     256
#define TAG     64
#define LM_D    200
#define POS_D   6
#define CAP_D   3
#define HB      (H_D * B_D)
#define GATE_M  (4 * H_D)
#define TI_M    (3 * H_D)
#define NCTA    128

#define SEC_Y   ((size_t)B_D * T_STEPS * TAG)
#define OFF_LF  ((size_t)0)
#define OFF_LC  (SEC_Y)
#define OFF_YF  (2 * SEC_Y)
#define OFF_YC  (3 * SEC_Y)
#define OFF_TS  (4 * SEC_Y)

// ------------------------- scratch (device globals) -------------------------
__device__ float g_x    [(size_t)T_STEPS * IN_D   * B_D];
__device__ float g_pre  [(size_t)T_STEPS * GATE_M * B_D];
__device__ float g_tiC  [(size_t)T_STEPS * TI_M   * B_D];
__device__ float g_hall [(size_t)T_STEPS * H_D    * B_D];
__device__ float g_Ts   [(size_t)T_STEPS * H_D    * B_D];
__device__ float g_c    [HB];
__device__ float g_opre [HB];
__device__ unsigned g_barcnt;
// k-major weights
__device__ float g_wfT  [(size_t)H_D * GATE_M];
__device__ float g_wiiT [(size_t)IN_D * GATE_M];
__device__ float g_wtiT [(size_t)H_D * TI_M];
__device__ float g_whtT [(size_t)H_D * H_D];
__device__ float g_wcoT [(size_t)H_D * H_D];
__device__ float g_wlmtT[(size_t)LM_D * H_D];
__device__ float g_wpostT[(size_t)POS_D * H_D];
__device__ float g_wcaptT[(size_t)CAP_D * H_D];
__device__ float g_wyfT [(size_t)H_D * TAG];
__device__ float g_wycT [(size_t)H_D * TAG];
__device__ float g_AlmT [(size_t)LM_D * TI_M];
__device__ float g_AposT[(size_t)POS_D * TI_M];
__device__ float g_AcapT[(size_t)CAP_D * TI_M];
__device__ float g_vc   [TI_M];

__device__ __forceinline__ float sigm(float x) { return 1.f / (1.f + expf(-x)); }

// ---------------------------------------------------------------------------
// 64/32-tile GEMM core (same as R3). A k-major, B k-major.
// ---------------------------------------------------------------------------
template <int BM, int BN, int BK, int TM, int TN>
__device__ __forceinline__ void gk(const float* __restrict__ A,
                                   const float* __restrict__ B,
                                   int K, int ldA, int ldB, int m0, int n0,
                                   float (&acc)[TM][TN], float* sm)
{
    static_assert((BM / TM) * (BN / TN) == 256, "");
    float (*As)[BM] = (float (*)[BM])sm;
    float (*Bs)[BN] = (float (*)[BN])(sm + BK * BM);
    const int tid = threadIdx.x;
    const int tx = tid % (BN / TN), ty = tid / (BN / TN);
    constexpr int AV = BM / 4, BV = BN / 4;
    constexpr int AL = (BM * BK / 4) / 256, BL = (BN * BK / 4) / 256;
    const float4 z4 = make_float4(0.f, 0.f, 0.f, 0.f);

    for (int k0 = 0; k0 < K; k0 += BK) {
#pragma unroll
        for (int i = 0; i < AL; i++) {
            int li = tid + i * 256, k = li / AV, m4 = (li % AV) * 4;
            float4 v = (k0 + k < K) ? *(const float4*)&A[(size_t)(k0 + k) * ldA + m0 + m4] : z4;
            *(float4*)&As[k][m4] = v;
        }
#pragma unroll
        for (int i = 0; i < BL; i++) {
            int li = tid + i * 256, k = li / BV, n4 = (li % BV) * 4;
            float4 v = (k0 + k < K) ? *(const float4*)&B[(size_t)(k0 + k) * ldB + n0 + n4] : z4;
            *(float4*)&Bs[k][n4] = v;
        }
        __syncthreads();
#pragma unroll
        for (int k = 0; k < BK; k++) {
            float a[TM], b[TN];
            if constexpr (TM % 4 == 0) {
#pragma unroll
                for (int i = 0; i < TM; i += 4) {
                    float4 v = *(const float4*)&As[k][ty * TM + i];
                    a[i] = v.x; a[i+1] = v.y; a[i+2] = v.z; a[i+3] = v.w;
                }
            } else {
                float2 v = *(const float2*)&As[k][ty * TM];
                a[0] = v.x; a[1] = v.y;
            }
            if constexpr (TN == 4) {
                float4 v = *(const float4*)&Bs[k][tx * 4];
                b[0] = v.x; b[1] = v.y; b[2] = v.z; b[3] = v.w;
            } else {
                float2 v = *(const float2*)&Bs[k][tx * 2];
                b[0] = v.x; b[1] = v.y;
            }
#pragma unroll
            for (int i = 0; i < TM; i++)
#pragma unroll
                for (int j = 0; j < TN; j++) acc[i][j] += a[i] * b[j];
        }
        __syncthreads();
    }
}

// ---------------------------------------------------------------------------
// 128x128x16 core, TM=8 TN=8 (for the big parallel GEMMs). smem 16KB.
// ---------------------------------------------------------------------------
__device__ __forceinline__ void gk128(const float* __restrict__ A,
                                      const float* __restrict__ B,
                                      int K, int ldA, int ldB, int m0, int n0,
                                      float (&acc)[8][8], float* sm)
{
    float (*As)[128] = (float (*)[128])sm;
    float (*Bs)[128] = (float (*)[128])(sm + 16 * 128);
    const int tid = threadIdx.x;
    const int tx = tid % 16, ty = tid / 16;
    const float4 z4 = make_float4(0.f, 0.f, 0.f, 0.f);

    for (int k0 = 0; k0 < K; k0 += 16) {
#pragma unroll
        for (int i = 0; i < 2; i++) {
            int li = tid + i * 256, k = li / 32, m4 = (li % 32) * 4;
            float4 va = (k0 + k < K) ? *(const float4*)&A[(size_t)(k0 + k) * ldA + m0 + m4] : z4;
            *(float4*)&As[k][m4] = va;
            float4 vb = (k0 + k < K) ? *(const float4*)&B[(size_t)(k0 + k) * ldB + n0 + m4] : z4;
            *(float4*)&Bs[k][m4] = vb;
        }
        __syncthreads();
#pragma unroll
        for (int k = 0; k < 16; k++) {
            float a[8], b[8];
            float4 v0 = *(const float4*)&As[k][ty * 8];
            float4 v1 = *(const float4*)&As[k][ty * 8 + 4];
            a[0]=v0.x; a[1]=v0.y; a[2]=v0.z; a[3]=v0.w; a[4]=v1.x; a[5]=v1.y; a[6]=v1.z; a[7]=v1.w;
            float4 w0 = *(const float4*)&Bs[k][tx * 8];
            float4 w1 = *(const float4*)&Bs[k][tx * 8 + 4];
            b[0]=w0.x; b[1]=w0.y; b[2]=w0.z; b[3]=w0.w; b[4]=w1.x; b[5]=w1.y; b[6]=w1.z; b[7]=w1.w;
#pragma unroll
            for (int i = 0; i < 8; i++)
#pragma unroll
                for (int j = 0; j < 8; j++) acc[i][j] += a[i] * b[j];
        }
        __syncthreads();
    }
}

// --------------------------- one-time precompute ---------------------------
__global__ void k_tr(const float* __restrict__ in, float* __restrict__ out, int M, int K)
{
    __shared__ float tl[32][33];
    int k0 = blockIdx.x * 32, m0 = blockIdx.y * 32;
    int tx = threadIdx.x, ty = threadIdx.y;
    for (int i = ty; i < 32; i += 8)
        if (m0 + i < M && k0 + tx < K) tl[i][tx] = in[(size_t)(m0 + i) * K + k0 + tx];
    __syncthreads();
    for (int i = ty; i < 32; i += 8)
        if (k0 + i < K && m0 + tx < M) out[(size_t)(k0 + i) * M + m0 + tx] = tl[tx][i];
}

__global__ void k_permii(const float* __restrict__ w_ii)
{
    __shared__ float tl[32][33];
    int p0 = blockIdx.x * 32, k0 = blockIdx.y * 32;
    int tx = threadIdx.x, ty = threadIdx.y;
    for (int i = ty; i < 32; i += 8) {
        int p = p0 + i, m = (p & 3) * H_D + (p >> 2);
        tl[i][tx] = w_ii[(size_t)m * IN_D + k0 + tx];
    }
    __syncthreads();
    for (int i = ty; i < 32; i += 8)
        g_wiiT[(size_t)(k0 + i) * GATE_M + p0 + tx] = tl[tx][i];
}

__global__ void __launch_bounds__(256)
k_w2(const float* __restrict__ w_hi, const float* __restrict__ w_ht)
{
    __shared__ float sm[16 * 128];
    int n0 = blockIdx.x * 64, m0 = blockIdx.y * 64;
    float acc[4][4] = {};
    gk<64,64,16,4,4>(g_wtiT, w_ht, H_D, TI_M, H_D, m0, n0, acc, sm);
    int tx = threadIdx.x % 16, ty = threadIdx.x / 16;
#pragma unroll
    for (int i = 0; i < 4; i++) {
        int m = m0 + ty * 4 + i;
        int p = (m & 511) * 4 + (m >> 9);
#pragma unroll
        for (int j = 0; j < 4; j++) {
            int jc = n0 + tx * 4 + j;
            g_wfT[(size_t)jc * GATE_M + p] = acc[i][j] + w_hi[(size_t)m * H_D + jc];
        }
    }
}

__global__ void k_fillo(const float* __restrict__ w_hi)
{
    int idx = blockIdx.x * 256 + threadIdx.x;
    if (idx >= H_D * H_D) return;
    int r = idx >> 9, j = idx & 511;
    g_wfT[(size_t)j * GATE_M + 4 * r + 3] = w_hi[(size_t)(3 * H_D + r) * H_D + j];
}

__global__ void k_small(const float* __restrict__ w_lmt, const float* __restrict__ w_post,
                        const float* __restrict__ w_capt, const float* __restrict__ b_i)
{
    int idx = blockIdx.x * 256 + threadIdx.x;
    if (idx < TI_M * LM_D) {
        int l = idx / TI_M, m = idx % TI_M;
        float s = 0.f;
        for (int k = 0; k < H_D; k++) s += g_wtiT[(size_t)k * TI_M + m] * w_lmt[k * LM_D + l];
        g_AlmT[(size_t)l * TI_M + m] = s;
    } else if (idx < TI_M * (LM_D + POS_D)) {
        int q = idx - TI_M * LM_D, l = q / TI_M, m = q % TI_M;
        float s = 0.f;
        for (int k = 0; k < H_D; k++) s += g_wtiT[(size_t)k * TI_M + m] * w_post[k * POS_D + l];
        g_AposT[(size_t)l * TI_M + m] = s;
    } else if (idx < TI_M * (LM_D + POS_D + CAP_D)) {
        int q = idx - TI_M * (LM_D + POS_D), l = q / TI_M, m = q % TI_M;
        float s = 0.f;
        for (int k = 0; k < H_D; k++) s += g_wtiT[(size_t)k * TI_M + m] * w_capt[k * CAP_D + l];
        g_AcapT[(size_t)l * TI_M + m] = s;
    } else if (idx < TI_M * (LM_D + POS_D + CAP_D + 1)) {
        int m = idx - TI_M * (LM_D + POS_D + CAP_D);
        float s = 0.f;
        for (int k = 0; k < H_D; k++) s += g_wtiT[(size_t)k * TI_M + m] * b_i[4 * H_D + k];
        g_vc[m] = s;
    }
}

__global__ void k_init(const float* __restrict__ c0)
{
    int i = blockIdx.x * 256 + threadIdx.x;
    if (i < HB) g_c[i] = c0[i];
    if (i == 0) g_barcnt = 0u;
}

// ------------------------------ phase A ------------------------------------
__global__ void __launch_bounds__(256, 2)
k_x(const float* __restrict__ inputs, const float* __restrict__ lms,
    const float* __restrict__ poses, const float* __restrict__ caps,
    const float* __restrict__ w_lmw, const float* __restrict__ w_posw,
    const float* __restrict__ w_capw)
{
    __shared__ float sm[2 * 16 * 128];
    int t = blockIdx.z, m0 = blockIdx.y * 128, n0 = blockIdx.x * 128;
    float acc[8][8] = {};
    gk128(w_lmw,  lms   + (size_t)t * LM_D  * B_D, LM_D,  IN_D, B_D, m0, n0, acc, sm);
    gk128(w_posw, poses + (size_t)t * POS_D * B_D, POS_D, IN_D, B_D, m0, n0, acc, sm);
    gk128(w_capw, caps  + (size_t)t * CAP_D * B_D, CAP_D, IN_D, B_D, m0, n0, acc, sm);
    int tx = threadIdx.x % 16, ty = threadIdx.x / 16;
    size_t base = (size_t)t * IN_D * B_D;
#pragma unroll
    for (int i = 0; i < 8; i++) {
        size_t idx = base + (size_t)(m0 + ty * 8 + i) * B_D + n0 + tx * 8;
#pragma unroll
        for (int q = 0; q < 2; q++) {
            float4 v = *(const float4*)&inputs[idx + q * 4];
            *(float4*)&g_x[idx + q * 4] = make_float4(acc[i][q*4] + v.x, acc[i][q*4+1] + v.y,
                                                      acc[i][q*4+2] + v.z, acc[i][q*4+3] + v.w);
        }
    }
}

__global__ void __launch_bounds__(256, 2)
k_tiC(const float* __restrict__ lms, const float* __restrict__ poses,
      const float* __restrict__ caps, const float* __restrict__ t0)
{
    __shared__ float sm[2 * 16 * 128];
    int t = blockIdx.z, m0 = blockIdx.y * 128, n0 = blockIdx.x * 128;
    float acc[8][8] = {};
    if (t == 0) {
        gk128(g_wtiT, t0, H_D, TI_M, B_D, m0, n0, acc, sm);
    } else {
        gk128(g_AlmT,  lms   + (size_t)(t-1) * LM_D  * B_D, LM_D,  TI_M, B_D, m0, n0, acc, sm);
        gk128(g_AposT, poses + (size_t)(t-1) * POS_D * B_D, POS_D, TI_M, B_D, m0, n0, acc, sm);
        gk128(g_AcapT, caps  + (size_t)(t-1) * CAP_D * B_D, CAP_D, TI_M, B_D, m0, n0, acc, sm);
    }
    int tx = threadIdx.x % 16, ty = threadIdx.x / 16;
    size_t base = (size_t)t * TI_M * B_D;
#pragma unroll
    for (int i = 0; i < 8; i++) {
        int m = m0 + ty * 8 + i;
        float vc = (t == 0) ? 0.f : g_vc[m];
        size_t idx = base + (size_t)m * B_D + n0 + tx * 8;
#pragma unroll
        for (int q = 0; q < 2; q++)
            *(float4*)&g_tiC[idx + q * 4] = make_float4(acc[i][q*4] + vc, acc[i][q*4+1] + vc,
                                                        acc[i][q*4+2] + vc, acc[i][q*4+3] + vc);
    }
}

__global__ void __launch_bounds__(256, 2)
k_ii(const float* __restrict__ b_i)
{
    __shared__ float sm[2 * 16 * 128];
    int t = blockIdx.z, m0 = blockIdx.y * 128, n0 = blockIdx.x * 128;
    float acc[8][8] = {};
    gk128(g_wiiT, g_x + (size_t)t * IN_D * B_D, IN_D, GATE_M, B_D, m0, n0, acc, sm);
    int tx = threadIdx.x % 16, ty = threadIdx.x / 16;
    size_t base = (size_t)t * GATE_M * B_D;
    size_t tib  = (size_t)t * TI_M * B_D;
#pragma unroll
    for (int i = 0; i < 8; i++) {
        int m = m0 + ty * 8 + i;
        int g = m & 3, r = m >> 2;
        float bb = b_i[g * H_D + r];
        size_t oidx = base + (size_t)m * B_D + n0 + tx * 8;
#pragma unroll
        for (int q = 0; q < 2; q++) {
            float4 tc = make_float4(0.f, 0.f, 0.f, 0.f);
            if (g < 3) tc = *(const float4*)&g_tiC[tib + (size_t)(g * H_D + r) * B_D + n0 + tx * 8 + q * 4];
            *(float4*)&g_pre[oidx + q * 4] = make_float4(acc[i][q*4] + tc.x + bb, acc[i][q*4+1] + tc.y + bb,
                                                         acc[i][q*4+2] + tc.z + bb, acc[i][q*4+3] + tc.w + bb);
        }
    }
}

// --------------------- persistent serial loop (one kernel) ------------------
__device__ __forceinline__ void grid_bar(unsigned target)
{
    __syncthreads();
    if (threadIdx.x == 0) {
        __threadfence();
        atomicAdd(&g_barcnt, 1u);
        while (*((volatile unsigned*)&g_barcnt) < target) __nanosleep(64);
    }
    __syncthreads();
    __threadfence();   // gpu-scope fence -> CCTL.IVALL: invalidate stale L1 lines
}

__global__ void __launch_bounds__(256)
k_loop(const float* __restrict__ h0)
{
    __shared__ float sm[2048];
    const int cta = blockIdx.x;
    const int tx = threadIdx.x % 16, ty = threadIdx.x / 16;
    unsigned gen = 0;

    for (int t = 0; t < T_STEPS; t++) {
        const float* hprev = (t == 0) ? h0 : (g_hall + (size_t)(t - 1) * HB);
        // ---- phase 1: gates + c update ----
        {
            int m0 = (cta >> 2) * 64, n0 = (cta & 3) * 64;
            float acc[4][4] = {};
            gk<64,64,16,4,4>(g_wfT, hprev, H_D, GATE_M, B_D, m0, n0, acc, sm);
            int r = (m0 + ty * 4) >> 2;
            int col = n0 + tx * 4;
            size_t base = (size_t)t * GATE_M * B_D + (size_t)(m0 + ty * 4) * B_D + col;
            float4 pi = *(const float4*)&g_pre[base];
            float4 pf = *(const float4*)&g_pre[base + B_D];
            float4 pz = *(const float4*)&g_pre[base + 2 * B_D];
            float4 po = *(const float4*)&g_pre[base + 3 * B_D];
            float4 co = *(const float4*)&g_c[r * B_D + col];
            float pia[4] = {pi.x, pi.y, pi.z, pi.w}, pfa[4] = {pf.x, pf.y, pf.z, pf.w};
            float pza[4] = {pz.x, pz.y, pz.z, pz.w}, poa[4] = {po.x, po.y, po.z, po.w};
            float coa[4] = {co.x, co.y, co.z, co.w};
            float cn[4], op[4];
#pragma unroll
            for (int j = 0; j < 4; j++) {
                float ig = sigm(acc[0][j] + pia[j]);
                float fg = sigm(acc[1][j] + pfa[j]);
                float zg = tanhf(acc[2][j] + pza[j]);
                cn[j] = fg * coa[j] + ig * zg;
                op[j] = acc[3][j] + poa[j];
            }
            *(float4*)&g_c[r * B_D + col]    = make_float4(cn[0], cn[1], cn[2], cn[3]);
            *(float4*)&g_opre[r * B_D + col] = make_float4(op[0], op[1], op[2], op[3]);
        }
        grid_bar(++gen * NCTA);
        // ---- phase 2: o gate + h ----
        {
            int m0 = (cta >> 3) * 32, n0 = (cta & 7) * 32;
            float acc[2][2] = {};
            gk<32,32,32,2,2>(g_wcoT, g_c, H_D, H_D, B_D, m0, n0, acc, sm);
            size_t hb = (size_t)t * HB;
#pragma unroll
            for (int i = 0; i < 2; i++)
#pragma unroll
                for (int j = 0; j < 2; j++) {
                    int rb = (m0 + ty * 2 + i) * B_D + n0 + tx * 2 + j;
                    float o = sigm(acc[i][j] + g_opre[rb]);
                    g_hall[hb + rb] = o * tanhf(g_c[rb]);
                }
        }
        grid_bar(++gen * NCTA);
    }
}

// ------------------------------ phase C ------------------------------------
// Ts[t] = w_ht@h[t] + b5 + (w_lmt@lm + w_post@pos + w_capt@cap); writes Ts + (b,t,h) out
__global__ void __launch_bounds__(256, 2)
k_Ts(const float* __restrict__ b_i, const float* __restrict__ lms,
     const float* __restrict__ poses, const float* __restrict__ caps,
     float* __restrict__ out)
{
    __shared__ float sm[2 * 16 * 128];
    int t = blockIdx.z, m0 = blockIdx.y * 128, n0 = blockIdx.x * 128;
    float acc[8][8] = {};
    gk128(g_whtT,   g_hall + (size_t)t * HB,            H_D,   H_D, B_D, m0, n0, acc, sm);
    gk128(g_wlmtT,  lms   + (size_t)t * LM_D  * B_D,    LM_D,  H_D, B_D, m0, n0, acc, sm);
    gk128(g_wpostT, poses + (size_t)t * POS_D * B_D,    POS_D, H_D, B_D, m0, n0, acc, sm);
    gk128(g_wcaptT, caps  + (size_t)t * CAP_D * B_D,    CAP_D, H_D, B_D, m0, n0, acc, sm);
    int tx = threadIdx.x % 16, ty = threadIdx.x / 16;
    size_t base = (size_t)t * HB;
    float v[8][8];
#pragma unroll
    for (int i = 0; i < 8; i++) {
        int h = m0 + ty * 8 + i;
        float bb = b_i[4 * H_D + h];
#pragma unroll
        for (int j = 0; j < 8; j++) v[i][j] = acc[i][j] + bb;
        size_t idx = base + (size_t)h * B_D + n0 + tx * 8;
        *(float4*)&g_Ts[idx]     = make_float4(v[i][0], v[i][1], v[i][2], v[i][3]);
        *(float4*)&g_Ts[idx + 4] = make_float4(v[i][4], v[i][5], v[i][6], v[i][7]);
    }
#pragma unroll
    for (int j = 0; j < 8; j++) {
        int b = n0 + tx * 8 + j;
        size_t o = OFF_TS + ((size_t)b * T_STEPS + t) * H_D + m0 + ty * 8;
        *(float4*)&out[o]     = make_float4(v[0][j], v[1][j], v[2][j], v[3][j]);
        *(float4*)&out[o + 4] = make_float4(v[4][j], v[5][j], v[6][j], v[7][j]);
    }
}

__global__ void __launch_bounds__(256)
k_y(const float* __restrict__ byf, const float* __restrict__ byc, float* __restrict__ out)
{
    __shared__ float sm[2 * 64 * 68];
    int t = blockIdx.y, n0 = blockIdx.x * 64;
    const float* Tst = g_Ts + (size_t)t * HB;
    float aF[4][4] = {}, aC[4][4] = {};
    gk<64,64,16,4,4>(g_wyfT, Tst, H_D, TAG, B_D, 0, n0, aF, sm);
    gk<64,64,16,4,4>(g_wycT, Tst, H_D, TAG, B_D, 0, n0, aC, sm);
    float (*yF)[68] = (float (*)[68])sm;
    float (*yC)[68] = (float (*)[68])(sm + 64 * 68);
    int tx = threadIdx.x % 16, ty = threadIdx.x / 16;
#pragma unroll
    for (int i = 0; i < 4; i++)
#pragma unroll
        for (int j = 0; j < 4; j++) {
            int m = ty * 4 + i, n = tx * 4 + j;
            yF[m][n] = aF[i][j] + byf[m];
            yC[m][n] = aC[i][j] + byc[m];
        }
    __syncthreads();
    if (threadIdx.x < 64) {
        int col = threadIdx.x, b = n0 + col;
        float mxF = -1e30f, mxC = -1e30f;
#pragma unroll
        for (int m = 0; m < TAG; m++) {
            mxF = fmaxf(mxF, yF[m][col]);
            mxC = fmaxf(mxC, yC[m][col]);
        }
        float sF = 0.f, sC = 0.f;
#pragma unroll
        for (int m = 0; m < TAG; m++) {
            sF += expf(yF[m][col] - mxF);
            sC += expf(yC[m][col] - mxC);
        }
        float lseF = mxF + logf(sF), lseC = mxC + logf(sC);
        size_t base = ((size_t)b * T_STEPS + t) * TAG;
#pragma unroll
        for (int m = 0; m < TAG; m++) {
            float vf = yF[m][col], vc = yC[m][col];
            out[OFF_LF + base + m] = vf - lseF;
            out[OFF_LC + base + m] = vc - lseC;
            out[OFF_YF + base + m] = vf;
            out[OFF_YC + base + m] = vc;
        }
    }
}

// ------------------------------- launch ------------------------------------
extern "C" void kernel_launch(void* const* d_in, const int* in_sizes, int n_in,
                              void* d_out, int out_size)
{
    const float* inputs   = (const float*)d_in[0];
    const float* lms      = (const float*)d_in[1];
    const float* poses    = (const float*)d_in[2];
    const float* caps     = (const float*)d_in[3];
    const float* h0       = (const float*)d_in[4];
    const float* c0       = (const float*)d_in[5];
    const float* t0       = (const float*)d_in[6];
    const float* w_ii     = (const float*)d_in[7];
    const float* w_hi     = (const float*)d_in[8];
    const float* w_ti     = (const float*)d_in[9];
    const float* w_co     = (const float*)d_in[10];
    const float* w_ht     = (const float*)d_in[11];
    const float* b_i      = (const float*)d_in[12];
    const float* b_y_fact = (const float*)d_in[14];
    const float* b_y_cond = (const float*)d_in[16];
    const float* w_lmw    = (const float*)d_in[17];
    const float* w_posw   = (const float*)d_in[18];
    const float* w_capw   = (const float*)d_in[19];
    const float* w_lmt    = (const float*)d_in[20];
    const float* w_post   = (const float*)d_in[21];
    const float* w_capt   = (const float*)d_in[22];
    float* out = (float*)d_out;

    float* p;
    dim3 tb(32, 8);
    cudaGetSymbolAddress((void**)&p, g_wtiT);
    k_tr<<<dim3(16, 48), tb>>>(w_ti, p, TI_M, H_D);
    cudaGetSymbolAddress((void**)&p, g_whtT);
    k_tr<<<dim3(16, 16), tb>>>(w_ht, p, H_D, H_D);
    cudaGetSymbolAddress((void**)&p, g_wcoT);
    k_tr<<<dim3(16, 16), tb>>>(w_co, p, H_D, H_D);
    cudaGetSymbolAddress((void**)&p, g_wlmtT);
    k_tr<<<dim3(7, 16), tb>>>(w_lmt, p, H_D, LM_D);
    cudaGetSymbolAddress((void**)&p, g_wpostT);
    k_tr<<<dim3(1, 16), tb>>>(w_post, p, H_D, POS_D);
    cudaGetSymbolAddress((void**)&p, g_wcaptT);
    k_tr<<<dim3(1, 16), tb>>>(w_capt, p, H_D, CAP_D);
    cudaGetSymbolAddress((void**)&p, g_wyfT);
    k_tr<<<dim3(16, 2), tb>>>((const float*)d_in[13], p, TAG, H_D);
    cudaGetSymbolAddress((void**)&p, g_wycT);
    k_tr<<<dim3(16, 2), tb>>>((const float*)d_in[15], p, TAG, H_D);

    k_permii<<<dim3(64, 16), tb>>>(w_ii);
    k_w2    <<<dim3(8, 24), 256>>>(w_hi, w_ht);
    k_fillo <<<1024, 256>>>(w_hi);
    k_small <<<(TI_M * (LM_D + POS_D + CAP_D + 1) + 255) / 256, 256>>>(w_lmt, w_post, w_capt, b_i);
    k_init  <<<HB / 256, 256>>>(c0);

    k_x   <<<dim3(2, 4,  T_STEPS), 256>>>(inputs, lms, poses, caps, w_lmw, w_posw, w_capw);
    k_tiC <<<dim3(2, 12, T_STEPS), 256>>>(lms, poses, caps, t0);
    k_ii  <<<dim3(2, 16, T_STEPS), 256>>>(b_i);

    k_loop<<<NCTA, 256>>>(h0);

    k_Ts<<<dim3(2, 4, T_STEPS), 256>>>(b_i, lms, poses, caps, out);
    k_y <<<dim3(4, T_STEPS), 256>>>(b_y_fact, b_y_cond, out);
}